// round 11
// baseline (speedup 1.0000x reference)
#include <cuda_runtime.h>
#include <cuda_bf16.h>
#include <math.h>

// Problem dims
#define Bc 32
#define Sc 512
#define Ic 256
#define Hc 1024
#define Oc 256
#define HID_OFF (Bc*Sc*Oc)   // floats: out (B,S,O) first, then hidden (B,2,H)
#define THREADS 512
#define REDROWS 112          // p1: 2 groups x 7 kq x 8 slots; p2: 15 warps x 7 slots

// ---------------- scratch (__device__ globals: allocation-free) ----------------
// layout of all [S][H][B] tensors: idx = (t*Hc + j)*Bc + b
__device__ float g_xz[Sc*Hc*Bc];
__device__ float g_xr[Sc*Hc*Bc];
__device__ float g_xg[Sc*Hc*Bc];
__device__ float g_y [Sc*Hc*Bc];
__device__ float g_h [Hc*Bc];    // [j][b]
__device__ float g_rh[Hc*Bc];    // [j][b]

// ---------------- two-level grid barrier state ----------------
__device__ unsigned g_sub[16];
__device__ unsigned g_master;
__device__ unsigned g_gen;

__device__ __forceinline__ unsigned ld_acq(const unsigned* p) {
    unsigned v;
    asm volatile("ld.acquire.gpu.u32 %0, [%1];" : "=r"(v) : "l"(p) : "memory");
    return v;
}
__device__ __forceinline__ void st_rel(unsigned* p, unsigned v) {
    asm volatile("st.release.gpu.u32 [%0], %1;" :: "l"(p), "r"(v) : "memory");
}
__device__ __forceinline__ void st_rlx(unsigned* p, unsigned v) {
    asm volatile("st.relaxed.gpu.u32 [%0], %1;" :: "l"(p), "r"(v) : "memory");
}
__device__ __forceinline__ unsigned atom_add_acqrel(unsigned* p, unsigned v) {
    unsigned o;
    asm volatile("atom.add.acq_rel.gpu.u32 %0, [%1], %2;" : "=r"(o) : "l"(p), "r"(v) : "memory");
    return o;
}

// All blocks must call with the same monotonically increasing target.
__device__ __forceinline__ void grid_bar(int bid, int NB, unsigned target) {
    __syncthreads();
    if (threadIdx.x == 0) {
        int s = bid & 15;
        unsigned quota = (unsigned)((NB - 1 - s) / 16 + 1);
        unsigned o = atom_add_acqrel(&g_sub[s], 1u);
        if (o == quota - 1u) {
            st_rlx(&g_sub[s], 0u);
            unsigned nsub = (unsigned)((NB < 16) ? NB : 16);
            unsigned m = atom_add_acqrel(&g_master, 1u);
            if (m == nsub - 1u) {
                st_rlx(&g_master, 0u);
                st_rel(&g_gen, target);
            }
        }
        while ((int)(ld_acq(&g_gen) - target) < 0) { }
    }
    __syncthreads();
}

__device__ __forceinline__ float sigm(float x) {
    return 1.0f / (1.0f + __expf(-x));
}
__device__ __forceinline__ float fast_tanh(float x) {
    float ax = fabsf(x);
    float e = __expf(2.0f * ax);
    float t = 1.0f - 2.0f / (e + 1.0f);   // e=inf -> 1
    return copysignf(t, x);
}

// ---------------- mbarrier + bulk-copy helpers ----------------
__device__ __forceinline__ unsigned s2u(const void* p) {
    unsigned a;
    asm("{ .reg .u64 t; cvta.to.shared.u64 t, %1; cvt.u32.u64 %0, t; }" : "=r"(a) : "l"(p));
    return a;
}
__device__ __forceinline__ void mb_init(unsigned a) {
    asm volatile("mbarrier.init.shared.b64 [%0], 1;" :: "r"(a) : "memory");
}
__device__ __forceinline__ void mb_expect(unsigned a, unsigned bytes) {
    asm volatile("mbarrier.arrive.expect_tx.shared.b64 _, [%0], %1;" :: "r"(a), "r"(bytes) : "memory");
}
__device__ __forceinline__ void g2s(unsigned dst, const float* src, unsigned bytes, unsigned mb) {
    asm volatile("cp.async.bulk.shared::cta.global.mbarrier::complete_tx::bytes [%0], [%1], %2, [%3];"
                 :: "r"(dst), "l"(src), "r"(bytes), "r"(mb) : "memory");
}
__device__ __forceinline__ void mb_wait(unsigned a, unsigned parity) {
    unsigned done;
    asm volatile("{\n\t.reg .pred p;\n\t"
                 "mbarrier.try_wait.parity.acquire.cta.shared::cta.b64 p, [%1], %2;\n\t"
                 "selp.b32 %0, 1, 0, p;\n\t}"
                 : "=r"(done) : "r"(a), "r"(parity) : "memory");
    while (!done) {
        asm volatile("{\n\t.reg .pred p;\n\t"
                     "mbarrier.try_wait.parity.acquire.cta.shared::cta.b64 p, [%1], %2, 0x989680;\n\t"
                     "selp.b32 %0, 1, 0, p;\n\t}"
                     : "=r"(done) : "r"(a), "r"(parity) : "memory");
    }
}

// packed f32x2 helpers (proj kernels)
__device__ __forceinline__ unsigned long long dup2(float w) {
    unsigned long long d;
    unsigned r = __float_as_uint(w);
    asm("mov.b64 %0, {%1, %1};" : "=l"(d) : "r"(r));
    return d;
}
#define FMA2(acc, h, w) asm("fma.rn.f32x2 %0, %1, %2, %0;" : "+l"(acc) : "l"(h), "l"(w))
#define LDSV2B64(h01, h23, addr) \
    asm("ld.shared.v2.b64 {%0, %1}, [%2];" : "=l"(h01), "=l"(h23) : "r"(addr))
#define UNPK2(r0, r1, a) asm("mov.b64 {%0, %1}, %2;" : "=r"(r0), "=r"(r1) : "l"(a))

// ---------------- input projection GEMM (f32x2 packed, R9-proven) ----------------
__global__ void __launch_bounds__(256) proj_kernel(
    const float* __restrict__ X,
    const float* __restrict__ W0, const float* __restrict__ bv0,
    const float* __restrict__ W1, const float* __restrict__ bv1,
    const float* __restrict__ W2, const float* __restrict__ bv2,
    int K, int alayout)
{
    __shared__ __align__(16) float A_sm[32 * 36];
    __shared__ __align__(16) float W_sm[32 * 132];

    const int t = blockIdx.x;
    const int j0 = blockIdx.y * 128;
    const int gate = blockIdx.z;
    const float* W    = (gate == 0) ? W0  : (gate == 1) ? W1  : W2;
    const float* bias = (gate == 0) ? bv0 : (gate == 1) ? bv1 : bv2;
    float* out        = (gate == 0) ? g_xz : (gate == 1) ? g_xr : g_xg;

    const int tid = threadIdx.x;
    const int jg = tid & 31;
    const int bg = tid >> 5;

    unsigned long long acc01[4], acc23[4];
#pragma unroll
    for (int jq = 0; jq < 4; jq++) {
        unsigned long long bv = dup2(bias[j0 + jg * 4 + jq]);
        acc01[jq] = bv; acc23[jq] = bv;
    }

    const unsigned aBase = s2u(A_sm) + (unsigned)(bg * 16);

    for (int k0 = 0; k0 < K; k0 += 32) {
        if (alayout == 0) {
            int kk = tid & 31, br = tid >> 5;
#pragma unroll
            for (int p = 0; p < 4; p++) {
                int b = br + p * 8;
                A_sm[kk * 36 + b] = X[((size_t)b * Sc + t) * K + k0 + kk];
            }
        } else {
            int b = tid & 31, kr = tid >> 5;
#pragma unroll
            for (int p = 0; p < 4; p++) {
                int kk = kr + p * 8;
                A_sm[kk * 36 + b] = g_y[((size_t)t * K + k0 + kk) * Bc + b];
            }
        }
        {
            int kk = tid & 31, jr = tid >> 5;
#pragma unroll
            for (int p = 0; p < 16; p++) {
                int jj = jr + p * 8;
                W_sm[kk * 132 + jj] = W[(size_t)(j0 + jj) * K + k0 + kk];
            }
        }
        __syncthreads();

#pragma unroll 8
        for (int kk = 0; kk < 32; kk++) {
            float4 wv = *(const float4*)(W_sm + kk * 132 + jg * 4);
            unsigned long long a01, a23;
            LDSV2B64(a01, a23, aBase + (unsigned)(kk * 144));
            unsigned long long w0 = dup2(wv.x), w1 = dup2(wv.y);
            unsigned long long w2 = dup2(wv.z), w3 = dup2(wv.w);
            FMA2(acc01[0], a01, w0); FMA2(acc23[0], a23, w0);
            FMA2(acc01[1], a01, w1); FMA2(acc23[1], a23, w1);
            FMA2(acc01[2], a01, w2); FMA2(acc23[2], a23, w2);
            FMA2(acc01[3], a01, w3); FMA2(acc23[3], a23, w3);
        }
        __syncthreads();
    }

#pragma unroll
    for (int jq = 0; jq < 4; jq++) {
        int j = j0 + jg * 4 + jq;
        unsigned r0, r1, r2, r3;
        UNPK2(r0, r1, acc01[jq]);
        UNPK2(r2, r3, acc23[jq]);
        float4 v = make_float4(__uint_as_float(r0), __uint_as_float(r1),
                               __uint_as_float(r2), __uint_as_float(r3));
        *(float4*)&out[((size_t)t * Hc + j) * Bc + bg * 4] = v;
    }
}

// ---------------- output projection (f32x2 packed, R9-proven) ----------------
__global__ void __launch_bounds__(256) outproj_kernel(
    const float* __restrict__ Wout, const float* __restrict__ bout,
    float* __restrict__ dout)
{
    __shared__ __align__(16) float A_sm[32 * 36];
    __shared__ __align__(16) float W_sm[32 * 132];

    const int t = blockIdx.x;
    const int j0 = blockIdx.y * 128;
    const int tid = threadIdx.x;
    const int jg = tid & 31;
    const int bg = tid >> 5;
    const int K = Hc;

    unsigned long long acc01[4], acc23[4];
#pragma unroll
    for (int jq = 0; jq < 4; jq++) {
        unsigned long long bv = dup2(bout[j0 + jg * 4 + jq]);
        acc01[jq] = bv; acc23[jq] = bv;
    }

    const unsigned aBase = s2u(A_sm) + (unsigned)(bg * 16);

    for (int k0 = 0; k0 < K; k0 += 32) {
        {
            int b = tid & 31, kr = tid >> 5;
#pragma unroll
            for (int p = 0; p < 4; p++) {
                int kk = kr + p * 8;
                A_sm[kk * 36 + b] = g_y[((size_t)t * K + k0 + kk) * Bc + b];
            }
        }
        {
            int kk = tid & 31, jr = tid >> 5;
#pragma unroll
            for (int p = 0; p < 16; p++) {
                int jj = jr + p * 8;
                W_sm[kk * 132 + jj] = Wout[(size_t)(j0 + jj) * K + k0 + kk];
            }
        }
        __syncthreads();

#pragma unroll 8
        for (int kk = 0; kk < 32; kk++) {
            float4 wv = *(const float4*)(W_sm + kk * 132 + jg * 4);
            unsigned long long a01, a23;
            LDSV2B64(a01, a23, aBase + (unsigned)(kk * 144));
            unsigned long long w0 = dup2(wv.x), w1 = dup2(wv.y);
            unsigned long long w2 = dup2(wv.z), w3 = dup2(wv.w);
            FMA2(acc01[0], a01, w0); FMA2(acc23[0], a23, w0);
            FMA2(acc01[1], a01, w1); FMA2(acc23[1], a23, w1);
            FMA2(acc01[2], a01, w2); FMA2(acc23[2], a23, w2);
            FMA2(acc01[3], a01, w3); FMA2(acc23[3], a23, w3);
        }
        __syncthreads();
    }

    float vals[4][4];
#pragma unroll
    for (int jq = 0; jq < 4; jq++) {
        unsigned r0, r1, r2, r3;
        UNPK2(r0, r1, acc01[jq]);
        UNPK2(r2, r3, acc23[jq]);
        vals[jq][0] = __uint_as_float(r0); vals[jq][1] = __uint_as_float(r1);
        vals[jq][2] = __uint_as_float(r2); vals[jq][3] = __uint_as_float(r3);
    }
#pragma unroll
    for (int q = 0; q < 4; q++) {
        int b = bg * 4 + q;
        float4 v = make_float4(vals[0][q], vals[1][q], vals[2][q], vals[3][q]);
        *(float4*)&dout[((size_t)b * Sc + t) * Oc + j0 + jg * 4] = v;
    }
}

// ---------------- persistent recurrence kernel (widened slot groups) ----------------
// 512 threads = 16 warps. DMA staging (cp.async.bulk) of h / r*h in 4x32KB
// chunks + per-chunk mbarriers (unchanged from R4/R9).
// Phase 1 (z,r: n1<=16 slots): warp = g1*8 + kq1; group g1 in {0,1} owns
// slots 8g1..8g1+7; kq1 in [0,8) -> 128-k range (chunk kq1>>1). Per warp:
// 8 cols x 128 k -> per k4: 8 broadcast weight-f4 + 4 scalar h loads for
// 32 FMA-instr (was 4+4 per 16). Partials (kq1>0) -> red row (g1*7+kq1-1)*8+c.
// Finalize: warp 0 -> slots 0..7 (all z slots: zv/ho arrays in registers),
// warp 8 -> slots 8..13 (all r).
// Phase 2 (g: n2<=7 slots): every warp computes all n2 slots over a 64-k
// range (kq2=warp in [0,16), chunk kq2>>2). Partials (warp>0) -> row
// (warp-1)*7+c. Finalize: warp 0 only (has zv/ho from phase 1).
__global__ void __launch_bounds__(THREADS) recur_kernel(
    const float* __restrict__ Whz, const float* __restrict__ Whr,
    const float* __restrict__ Whg, int layer, float* __restrict__ dout)
{
    extern __shared__ float smem[];
    const int NB  = gridDim.x;
    const int bid = blockIdx.x;
    const int tid = threadIdx.x;
    const int warp = tid >> 5, lane = tid & 31;

    const int slotsMax = (2048 + NB - 1) / NB + (1024 + NB - 1) / NB;
    float* buf    = smem;                          // [1024][32] h or r*h
    float* w_sm   = smem + Hc * Bc;                // slotsMax rows x 1024
    float* red_sm = w_sm + (size_t)slotsMax * Hc;  // REDROWS x 32
    float* mb_f   = red_sm + REDROWS * 32;         // 8 mbarriers (64B)
    const unsigned mb0  = s2u(mb_f);               // h chunks: mb0+q*8
    const unsigned mbr0 = mb0 + 32;                // rh chunks: mbr0+q*8
    const unsigned bufa = s2u(buf);

    const int n1 = (2048 - bid + NB - 1) / NB;
    const int n2 = (1024 - bid + NB - 1) / NB;

    if (tid == 0) {
        for (int q = 0; q < 8; q++) mb_init(mb0 + q * 8);
        asm volatile("fence.proxy.async.shared::cta;" ::: "memory");
    }
    __syncthreads();

    // stage weights once (phase1: z rows then r rows; then g rows)
    for (int s = 0; s < n1; s++) {
        int c = bid + s * NB;
        const float4* src = (const float4*)((c < 1024) ? (Whz + (size_t)c * Hc)
                                                       : (Whr + (size_t)(c - 1024) * Hc));
        float4* dst = (float4*)(w_sm + (size_t)s * Hc);
        if (tid < 256) dst[tid] = src[tid];
    }
    for (int s = 0; s < n2; s++) {
        int j = bid + s * NB;
        const float4* src = (const float4*)(Whg + (size_t)j * Hc);
        float4* dst = (float4*)(w_sm + (size_t)(n1 + s) * Hc);
        if (tid < 256) dst[tid] = src[tid];
    }
    // zero h
    for (int i = bid * THREADS + tid; i < Hc * Bc; i += NB * THREADS)
        __stcg(&g_h[i], 0.0f);

    unsigned ep = ld_acq(&g_gen);
    ep++; grid_bar(bid, NB, ep);

    // kick off stage of h(-1) for step 0
    if (tid == 0) {
#pragma unroll
        for (int q = 0; q < 4; q++) {
            mb_expect(mb0 + q * 8, 32768u);
            g2s(bufa + q * 32768u, g_h + q * 8192, 32768u, mb0 + q * 8);
        }
    }

    const int g1  = warp >> 3;           // phase-1 group (0,1)
    const int kq1 = warp & 7;            // phase-1 k-split, 128 k
    const int kq2 = warp;                // phase-2 k-split, 64 k

    // contiguous-row weight bases (reads past n1/n2 land in allocated w_sm rows)
    const float4* wb1 = (const float4*)(w_sm + (size_t)(g1 * 8) * Hc + kq1 * 128);
    const float4* wb2 = (const float4*)(w_sm + (size_t)n1 * Hc + kq2 * 64);
    const int rowStep = Hc / 4;          // float4 stride between weight rows

    float zv[8], ho[8];
#pragma unroll
    for (int c = 0; c < 8; c++) { zv[c] = 0.f; ho[c] = 0.f; }

    for (int t = 0; t < Sc; t++) {
        const unsigned par = (unsigned)(t & 1);

        // prefetch x-projection inputs for this step's finalize
        float px[8];
#pragma unroll
        for (int c = 0; c < 8; c++) px[c] = 0.f;
        if (kq1 == 0) {   // warps 0 and 8
#pragma unroll
            for (int c = 0; c < 8; c++) {
                int s = g1 * 8 + c;
                if (s < n1) {
                    int cc = bid + s * NB;
                    bool isz = (s < n2);
                    int j = isz ? cc : cc - 1024;
                    px[c] = isz ? __ldcg(&g_xz[((size_t)t * Hc + j) * Bc + lane])
                                : __ldcg(&g_xr[((size_t)t * Hc + j) * Bc + lane]);
                }
            }
        }
        float pg[7];
#pragma unroll
        for (int c = 0; c < 7; c++) pg[c] = 0.f;
        if (warp == 0) {
#pragma unroll
            for (int c = 0; c < 7; c++) {
                if (c < n2) {
                    int j = bid + c * NB;
                    pg[c] = __ldcg(&g_xg[((size_t)t * Hc + j) * Bc + lane]);
                }
            }
        }

        // ---- phase 1 partials: 8 slots x 128 k per warp ----
        mb_wait(mb0 + (kq1 >> 1) * 8, par);
        float a[8];
#pragma unroll
        for (int c = 0; c < 8; c++) a[c] = 0.f;
        {
            const float* hp = buf + kq1 * 128 * Bc + lane;
#pragma unroll 2
            for (int k4 = 0; k4 < 32; k4++) {
                float v0 = hp[0], v1 = hp[Bc], v2 = hp[2 * Bc], v3 = hp[3 * Bc];
#pragma unroll
                for (int i = 0; i < 8; i++) {
                    float4 w = wb1[i * rowStep + k4];
                    a[i] += v0 * w.x; a[i] += v1 * w.y;
                    a[i] += v2 * w.z; a[i] += v3 * w.w;
                }
                hp += 4 * Bc;
            }
        }
        if (kq1 > 0) {
#pragma unroll
            for (int c = 0; c < 8; c++)
                red_sm[(size_t)((g1 * 7 + kq1 - 1) * 8 + c) * 32 + lane] = a[c];
        }
        __syncthreads();

        // finalize phase 1: warp 0 -> slots 0..7, warp 8 -> slots 8..15
        if (kq1 == 0) {
#pragma unroll
            for (int c = 0; c < 8; c++) {
                int s = g1 * 8 + c;
                if (s < n1) {
                    float acc = a[c] + px[c];
#pragma unroll
                    for (int p = 1; p < 8; p++)
                        acc += red_sm[(size_t)((g1 * 7 + p - 1) * 8 + c) * 32 + lane];
                    float val = sigm(acc);
                    int cc = bid + s * NB;
                    bool isz = (s < n2);
                    int j = isz ? cc : cc - 1024;
                    float hv = buf[j * Bc + lane];
                    if (isz) { zv[c] = val; ho[c] = hv; }
                    else     { __stcg(&g_rh[j * Bc + lane], val * hv); }
                }
            }
        }
        ep++; grid_bar(bid, NB, ep);

        // kick off stage of r*h (overwrites buf; all P1 reads done at grid_bar)
        if (tid == 0) {
#pragma unroll
            for (int q = 0; q < 4; q++) {
                mb_expect(mbr0 + q * 8, 32768u);
                g2s(bufa + q * 32768u, g_rh + q * 8192, 32768u, mbr0 + q * 8);
            }
        }

        // ---- phase 2 partials: all n2 slots x 64 k per warp ----
        mb_wait(mbr0 + (kq2 >> 2) * 8, par);
        float b[7];
#pragma unroll
        for (int c = 0; c < 7; c++) b[c] = 0.f;
        {
            const float* hp = buf + kq2 * 64 * Bc + lane;
#pragma unroll 2
            for (int k4 = 0; k4 < 16; k4++) {
                float v0 = hp[0], v1 = hp[Bc], v2 = hp[2 * Bc], v3 = hp[3 * Bc];
#pragma unroll
                for (int i = 0; i < 7; i++) {
                    float4 w = wb2[i * rowStep + k4];
                    b[i] += v0 * w.x; b[i] += v1 * w.y;
                    b[i] += v2 * w.z; b[i] += v3 * w.w;
                }
                hp += 4 * Bc;
            }
        }
        if (warp > 0) {
#pragma unroll
            for (int c = 0; c < 7; c++)
                red_sm[(size_t)((warp - 1) * 7 + c) * 32 + lane] = b[c];
        }
        __syncthreads();

        // finalize phase 2: warp 0 only (holds zv/ho for slots 0..6)
        if (warp == 0) {
#pragma unroll
            for (int c = 0; c < 7; c++) {
                if (c < n2) {
                    float acc = b[c] + pg[c];
#pragma unroll
                    for (int p = 1; p < 16; p++)
                        acc += red_sm[(size_t)((p - 1) * 7 + c) * 32 + lane];
                    float gg = fast_tanh(acc);
                    float hn = zv[c] * ho[c] + (1.0f - zv[c]) * gg;
                    int j = bid + c * NB;
                    __stcg(&g_h[j * Bc + lane], hn);
                    g_y[((size_t)t * Hc + j) * Bc + lane] = hn;
                }
            }
        }
        ep++; grid_bar(bid, NB, ep);

        // kick off stage of h(t) for step t+1 (overwrites buf; P2 reads done)
        if (tid == 0 && t + 1 < Sc) {
#pragma unroll
            for (int q = 0; q < 4; q++) {
                mb_expect(mb0 + q * 8, 32768u);
                g2s(bufa + q * 32768u, g_h + q * 8192, 32768u, mb0 + q * 8);
            }
        }
    }

    // write final hidden state for this layer: d_out[HID_OFF + b*2H + layer*H + j]
    for (int s = warp; s < n2; s += 16) {
        int j = bid + s * NB;
        dout[HID_OFF + (size_t)lane * (2 * Hc) + (size_t)layer * Hc + j] =
            __ldcg(&g_h[j * Bc + lane]);
    }
}

// ---------------- host ----------------
extern "C" void kernel_launch(void* const* d_in, const int* in_sizes, int n_in,
                              void* d_out, int out_size) {
    const float* x    = (const float*)d_in[0];
    const float* Wxz0 = (const float*)d_in[1];
    const float* bxz0 = (const float*)d_in[2];
    const float* Whz0 = (const float*)d_in[3];
    const float* Wxr0 = (const float*)d_in[4];
    const float* bxr0 = (const float*)d_in[5];
    const float* Whr0 = (const float*)d_in[6];
    const float* Wxg0 = (const float*)d_in[7];
    const float* bxg0 = (const float*)d_in[8];
    const float* Whg0 = (const float*)d_in[9];
    const float* Wxz1 = (const float*)d_in[10];
    const float* bxz1 = (const float*)d_in[11];
    const float* Whz1 = (const float*)d_in[12];
    const float* Wxr1 = (const float*)d_in[13];
    const float* bxr1 = (const float*)d_in[14];
    const float* Whr1 = (const float*)d_in[15];
    const float* Wxg1 = (const float*)d_in[16];
    const float* bxg1 = (const float*)d_in[17];
    const float* Whg1 = (const float*)d_in[18];
    const float* Wout = (const float*)d_in[19];
    const float* bout = (const float*)d_in[20];
    float* out = (float*)d_out;

    int dev = 0;
    cudaGetDevice(&dev);
    int sm = 148;
    cudaDeviceGetAttribute(&sm, cudaDevAttrMultiProcessorCount, dev);
    int NB = (sm < 148) ? sm : 148;
    int slots = (2048 + NB - 1) / NB + (1024 + NB - 1) / NB;
    size_t smemB = ((size_t)Hc * Bc + (size_t)slots * Hc + (size_t)REDROWS * 32 + 16)
                   * sizeof(float);
    cudaFuncSetAttribute(recur_kernel, cudaFuncAttributeMaxDynamicSharedMemorySize, (int)smemB);

    dim3 pg(Sc, Hc / 128, 3);

    // Layer 0
    proj_kernel<<<pg, 256>>>(x, Wxz0, bxz0, Wxr0, bxr0, Wxg0, bxg0, Ic, 0);
    recur_kernel<<<NB, THREADS, smemB>>>(Whz0, Whr0, Whg0, 0, out);
    // Layer 1 (input projections read g_y written by layer-0 recurrence)
    proj_kernel<<<pg, 256>>>(x, Wxz1, bxz1, Wxr1, bxr1, Wxg1, bxg1, Hc, 1);
    recur_kernel<<<NB, THREADS, smemB>>>(Whz1, Whr1, Whg1, 1, out);
    // Output projection
    dim3 og(Sc, Oc / 128, 1);
    outproj_kernel<<<og, 256>>>(Wout, bout, out);
}

// round 12
// speedup vs baseline: 1.0957x; 1.0957x over previous
#include <cuda_runtime.h>
#include <cuda_bf16.h>
#include <math.h>

// Problem dims
#define Bc 32
#define Sc 512
#define Ic 256
#define Hc 1024
#define Oc 256
#define HID_OFF (Bc*Sc*Oc)   // floats: out (B,S,O) first, then hidden (B,2,H)
#define THREADS 512
#define REDROWS 112          // p1: 16 warps x 7 (skip-diagonal); p2: 16 warps x 7

// ---------------- scratch (__device__ globals: allocation-free) ----------------
// layout of all [S][H][B] tensors: idx = (t*Hc + j)*Bc + b
__device__ float g_xz[Sc*Hc*Bc];
__device__ float g_xr[Sc*Hc*Bc];
__device__ float g_xg[Sc*Hc*Bc];
__device__ float g_y [Sc*Hc*Bc];
__device__ float g_h [Hc*Bc];    // [j][b]
__device__ float g_rh[Hc*Bc];    // [j][b]

// ---------------- two-level grid barrier state ----------------
__device__ unsigned g_sub[16];
__device__ unsigned g_master;
__device__ unsigned g_gen;

__device__ __forceinline__ unsigned ld_acq(const unsigned* p) {
    unsigned v;
    asm volatile("ld.acquire.gpu.u32 %0, [%1];" : "=r"(v) : "l"(p) : "memory");
    return v;
}
__device__ __forceinline__ void st_rel(unsigned* p, unsigned v) {
    asm volatile("st.release.gpu.u32 [%0], %1;" :: "l"(p), "r"(v) : "memory");
}
__device__ __forceinline__ void st_rlx(unsigned* p, unsigned v) {
    asm volatile("st.relaxed.gpu.u32 [%0], %1;" :: "l"(p), "r"(v) : "memory");
}
__device__ __forceinline__ unsigned atom_add_acqrel(unsigned* p, unsigned v) {
    unsigned o;
    asm volatile("atom.add.acq_rel.gpu.u32 %0, [%1], %2;" : "=r"(o) : "l"(p), "r"(v) : "memory");
    return o;
}

// All blocks must call with the same monotonically increasing target.
__device__ __forceinline__ void grid_bar(int bid, int NB, unsigned target) {
    __syncthreads();
    if (threadIdx.x == 0) {
        int s = bid & 15;
        unsigned quota = (unsigned)((NB - 1 - s) / 16 + 1);
        unsigned o = atom_add_acqrel(&g_sub[s], 1u);
        if (o == quota - 1u) {
            st_rlx(&g_sub[s], 0u);
            unsigned nsub = (unsigned)((NB < 16) ? NB : 16);
            unsigned m = atom_add_acqrel(&g_master, 1u);
            if (m == nsub - 1u) {
                st_rlx(&g_master, 0u);
                st_rel(&g_gen, target);
            }
        }
        while ((int)(ld_acq(&g_gen) - target) < 0) { }
    }
    __syncthreads();
}

__device__ __forceinline__ float sigm(float x) {
    return 1.0f / (1.0f + __expf(-x));
}
__device__ __forceinline__ float fast_tanh(float x) {
    float ax = fabsf(x);
    float e = __expf(2.0f * ax);
    float t = 1.0f - 2.0f / (e + 1.0f);   // e=inf -> 1
    return copysignf(t, x);
}

// ---------------- mbarrier + bulk-copy helpers ----------------
__device__ __forceinline__ unsigned s2u(const void* p) {
    unsigned a;
    asm("{ .reg .u64 t; cvta.to.shared.u64 t, %1; cvt.u32.u64 %0, t; }" : "=r"(a) : "l"(p));
    return a;
}
__device__ __forceinline__ void mb_init(unsigned a) {
    asm volatile("mbarrier.init.shared.b64 [%0], 1;" :: "r"(a) : "memory");
}
__device__ __forceinline__ void mb_expect(unsigned a, unsigned bytes) {
    asm volatile("mbarrier.arrive.expect_tx.shared.b64 _, [%0], %1;" :: "r"(a), "r"(bytes) : "memory");
}
__device__ __forceinline__ void g2s(unsigned dst, const float* src, unsigned bytes, unsigned mb) {
    asm volatile("cp.async.bulk.shared::cta.global.mbarrier::complete_tx::bytes [%0], [%1], %2, [%3];"
                 :: "r"(dst), "l"(src), "r"(bytes), "r"(mb) : "memory");
}
__device__ __forceinline__ void mb_wait(unsigned a, unsigned parity) {
    unsigned done;
    asm volatile("{\n\t.reg .pred p;\n\t"
                 "mbarrier.try_wait.parity.acquire.cta.shared::cta.b64 p, [%1], %2;\n\t"
                 "selp.b32 %0, 1, 0, p;\n\t}"
                 : "=r"(done) : "r"(a), "r"(parity) : "memory");
    while (!done) {
        asm volatile("{\n\t.reg .pred p;\n\t"
                     "mbarrier.try_wait.parity.acquire.cta.shared::cta.b64 p, [%1], %2, 0x989680;\n\t"
                     "selp.b32 %0, 1, 0, p;\n\t}"
                     : "=r"(done) : "r"(a), "r"(parity) : "memory");
    }
}

// packed f32x2 helpers (proj kernels)
__device__ __forceinline__ unsigned long long dup2(float w) {
    unsigned long long d;
    unsigned r = __float_as_uint(w);
    asm("mov.b64 %0, {%1, %1};" : "=l"(d) : "r"(r));
    return d;
}
#define FMA2(acc, h, w) asm("fma.rn.f32x2 %0, %1, %2, %0;" : "+l"(acc) : "l"(h), "l"(w))
#define LDSV2B64(h01, h23, addr) \
    asm("ld.shared.v2.b64 {%0, %1}, [%2];" : "=l"(h01), "=l"(h23) : "r"(addr))
#define UNPK2(r0, r1, a) asm("mov.b64 {%0, %1}, %2;" : "=r"(r0), "=r"(r1) : "l"(a))

// ---------------- input projection GEMM (f32x2 packed, R9-proven) ----------------
__global__ void __launch_bounds__(256) proj_kernel(
    const float* __restrict__ X,
    const float* __restrict__ W0, const float* __restrict__ bv0,
    const float* __restrict__ W1, const float* __restrict__ bv1,
    const float* __restrict__ W2, const float* __restrict__ bv2,
    int K, int alayout)
{
    __shared__ __align__(16) float A_sm[32 * 36];
    __shared__ __align__(16) float W_sm[32 * 132];

    const int t = blockIdx.x;
    const int j0 = blockIdx.y * 128;
    const int gate = blockIdx.z;
    const float* W    = (gate == 0) ? W0  : (gate == 1) ? W1  : W2;
    const float* bias = (gate == 0) ? bv0 : (gate == 1) ? bv1 : bv2;
    float* out        = (gate == 0) ? g_xz : (gate == 1) ? g_xr : g_xg;

    const int tid = threadIdx.x;
    const int jg = tid & 31;
    const int bg = tid >> 5;

    unsigned long long acc01[4], acc23[4];
#pragma unroll
    for (int jq = 0; jq < 4; jq++) {
        unsigned long long bv = dup2(bias[j0 + jg * 4 + jq]);
        acc01[jq] = bv; acc23[jq] = bv;
    }

    const unsigned aBase = s2u(A_sm) + (unsigned)(bg * 16);

    for (int k0 = 0; k0 < K; k0 += 32) {
        if (alayout == 0) {
            int kk = tid & 31, br = tid >> 5;
#pragma unroll
            for (int p = 0; p < 4; p++) {
                int b = br + p * 8;
                A_sm[kk * 36 + b] = X[((size_t)b * Sc + t) * K + k0 + kk];
            }
        } else {
            int b = tid & 31, kr = tid >> 5;
#pragma unroll
            for (int p = 0; p < 4; p++) {
                int kk = kr + p * 8;
                A_sm[kk * 36 + b] = g_y[((size_t)t * K + k0 + kk) * Bc + b];
            }
        }
        {
            int kk = tid & 31, jr = tid >> 5;
#pragma unroll
            for (int p = 0; p < 16; p++) {
                int jj = jr + p * 8;
                W_sm[kk * 132 + jj] = W[(size_t)(j0 + jj) * K + k0 + kk];
            }
        }
        __syncthreads();

#pragma unroll 8
        for (int kk = 0; kk < 32; kk++) {
            float4 wv = *(const float4*)(W_sm + kk * 132 + jg * 4);
            unsigned long long a01, a23;
            LDSV2B64(a01, a23, aBase + (unsigned)(kk * 144));
            unsigned long long w0 = dup2(wv.x), w1 = dup2(wv.y);
            unsigned long long w2 = dup2(wv.z), w3 = dup2(wv.w);
            FMA2(acc01[0], a01, w0); FMA2(acc23[0], a23, w0);
            FMA2(acc01[1], a01, w1); FMA2(acc23[1], a23, w1);
            FMA2(acc01[2], a01, w2); FMA2(acc23[2], a23, w2);
            FMA2(acc01[3], a01, w3); FMA2(acc23[3], a23, w3);
        }
        __syncthreads();
    }

#pragma unroll
    for (int jq = 0; jq < 4; jq++) {
        int j = j0 + jg * 4 + jq;
        unsigned r0, r1, r2, r3;
        UNPK2(r0, r1, acc01[jq]);
        UNPK2(r2, r3, acc23[jq]);
        float4 v = make_float4(__uint_as_float(r0), __uint_as_float(r1),
                               __uint_as_float(r2), __uint_as_float(r3));
        *(float4*)&out[((size_t)t * Hc + j) * Bc + bg * 4] = v;
    }
}

// ---------------- output projection (f32x2 packed, R9-proven) ----------------
__global__ void __launch_bounds__(256) outproj_kernel(
    const float* __restrict__ Wout, const float* __restrict__ bout,
    float* __restrict__ dout)
{
    __shared__ __align__(16) float A_sm[32 * 36];
    __shared__ __align__(16) float W_sm[32 * 132];

    const int t = blockIdx.x;
    const int j0 = blockIdx.y * 128;
    const int tid = threadIdx.x;
    const int jg = tid & 31;
    const int bg = tid >> 5;
    const int K = Hc;

    unsigned long long acc01[4], acc23[4];
#pragma unroll
    for (int jq = 0; jq < 4; jq++) {
        unsigned long long bv = dup2(bout[j0 + jg * 4 + jq]);
        acc01[jq] = bv; acc23[jq] = bv;
    }

    const unsigned aBase = s2u(A_sm) + (unsigned)(bg * 16);

    for (int k0 = 0; k0 < K; k0 += 32) {
        {
            int b = tid & 31, kr = tid >> 5;
#pragma unroll
            for (int p = 0; p < 4; p++) {
                int kk = kr + p * 8;
                A_sm[kk * 36 + b] = g_y[((size_t)t * K + k0 + kk) * Bc + b];
            }
        }
        {
            int kk = tid & 31, jr = tid >> 5;
#pragma unroll
            for (int p = 0; p < 16; p++) {
                int jj = jr + p * 8;
                W_sm[kk * 132 + jj] = Wout[(size_t)(j0 + jj) * K + k0 + kk];
            }
        }
        __syncthreads();

#pragma unroll 8
        for (int kk = 0; kk < 32; kk++) {
            float4 wv = *(const float4*)(W_sm + kk * 132 + jg * 4);
            unsigned long long a01, a23;
            LDSV2B64(a01, a23, aBase + (unsigned)(kk * 144));
            unsigned long long w0 = dup2(wv.x), w1 = dup2(wv.y);
            unsigned long long w2 = dup2(wv.z), w3 = dup2(wv.w);
            FMA2(acc01[0], a01, w0); FMA2(acc23[0], a23, w0);
            FMA2(acc01[1], a01, w1); FMA2(acc23[1], a23, w1);
            FMA2(acc01[2], a01, w2); FMA2(acc23[2], a23, w2);
            FMA2(acc01[3], a01, w3); FMA2(acc23[3], a23, w3);
        }
        __syncthreads();
    }

    float vals[4][4];
#pragma unroll
    for (int jq = 0; jq < 4; jq++) {
        unsigned r0, r1, r2, r3;
        UNPK2(r0, r1, acc01[jq]);
        UNPK2(r2, r3, acc23[jq]);
        vals[jq][0] = __uint_as_float(r0); vals[jq][1] = __uint_as_float(r1);
        vals[jq][2] = __uint_as_float(r2); vals[jq][3] = __uint_as_float(r3);
    }
#pragma unroll
    for (int q = 0; q < 4; q++) {
        int b = bg * 4 + q;
        float4 v = make_float4(vals[0][q], vals[1][q], vals[2][q], vals[3][q]);
        *(float4*)&dout[((size_t)b * Sc + t) * Oc + j0 + jg * 4] = v;
    }
}

// ---------------- persistent recurrence kernel ----------------
// 512 threads = 16 warps. DMA staging (cp.async.bulk) of h / r*h in 4x32KB
// chunks + per-chunk mbarriers (R4-proven).
// Compute (R11-proven wide groups):
//  Phase 1 (z,r: n1<=14 slots): warp = g1*8 + kq1; group g1 owns slots
//  8g1..8g1+7, kq1 in [0,8) -> 128-k range (chunk kq1>>1). 8 cols x 128 k.
//  Phase 2 (g: n2<=7 slots): warp = kq2 in [0,16) -> 64-k range (chunk kq2>>2),
//  all n2 slots per warp.
// NEW distributed finalize: warp w finalizes slot w (p1, w<n1) / g-slot w
//  (p2, w<n2). Warp w's own partial for slot w stays in register a[w&7];
//  only cross-kq partials go through red_sm:
//   p1: warp w stores a[c] (c != kq1) at row w*7 + (c<kq1 ? c : c-1)   (112 rows)
//   p2: warp w stores b[c] for all c<7 at row w*7 + c                  (112 rows)
// zv/ho are scalars: warp w<7 holds z-slot w -> carries to its p2 finalize.
__global__ void __launch_bounds__(THREADS) recur_kernel(
    const float* __restrict__ Whz, const float* __restrict__ Whr,
    const float* __restrict__ Whg, int layer, float* __restrict__ dout)
{
    extern __shared__ float smem[];
    const int NB  = gridDim.x;
    const int bid = blockIdx.x;
    const int tid = threadIdx.x;
    const int warp = tid >> 5, lane = tid & 31;

    const int slotsMax = (2048 + NB - 1) / NB + (1024 + NB - 1) / NB;
    float* buf    = smem;                          // [1024][32] h or r*h
    float* w_sm   = smem + Hc * Bc;                // slotsMax rows x 1024
    float* red_sm = w_sm + (size_t)slotsMax * Hc;  // REDROWS x 32
    float* mb_f   = red_sm + REDROWS * 32;         // 8 mbarriers (64B)
    const unsigned mb0  = s2u(mb_f);               // h chunks: mb0+q*8
    const unsigned mbr0 = mb0 + 32;                // rh chunks: mbr0+q*8
    const unsigned bufa = s2u(buf);

    const int n1 = (2048 - bid + NB - 1) / NB;
    const int n2 = (1024 - bid + NB - 1) / NB;

    if (tid == 0) {
        for (int q = 0; q < 8; q++) mb_init(mb0 + q * 8);
        asm volatile("fence.proxy.async.shared::cta;" ::: "memory");
    }
    __syncthreads();

    // stage weights once (phase1: z rows then r rows; then g rows)
    for (int s = 0; s < n1; s++) {
        int c = bid + s * NB;
        const float4* src = (const float4*)((c < 1024) ? (Whz + (size_t)c * Hc)
                                                       : (Whr + (size_t)(c - 1024) * Hc));
        float4* dst = (float4*)(w_sm + (size_t)s * Hc);
        if (tid < 256) dst[tid] = src[tid];
    }
    for (int s = 0; s < n2; s++) {
        int j = bid + s * NB;
        const float4* src = (const float4*)(Whg + (size_t)j * Hc);
        float4* dst = (float4*)(w_sm + (size_t)(n1 + s) * Hc);
        if (tid < 256) dst[tid] = src[tid];
    }
    // zero h
    for (int i = bid * THREADS + tid; i < Hc * Bc; i += NB * THREADS)
        __stcg(&g_h[i], 0.0f);

    unsigned ep = ld_acq(&g_gen);
    ep++; grid_bar(bid, NB, ep);

    // kick off stage of h(-1) for step 0
    if (tid == 0) {
#pragma unroll
        for (int q = 0; q < 4; q++) {
            mb_expect(mb0 + q * 8, 32768u);
            g2s(bufa + q * 32768u, g_h + q * 8192, 32768u, mb0 + q * 8);
        }
    }

    const int g1  = warp >> 3;           // phase-1 group (0,1)
    const int kq1 = warp & 7;            // phase-1 k-split, 128 k
    const int kq2 = warp;                // phase-2 k-split, 64 k

    const float4* wb1 = (const float4*)(w_sm + (size_t)(g1 * 8) * Hc + kq1 * 128);
    const float4* wb2 = (const float4*)(w_sm + (size_t)n1 * Hc + kq2 * 64);
    const int rowStep = Hc / 4;          // float4 stride between weight rows

    // this warp's finalize identity
    const int cw = warp & 7;             // own slot index within group (p1)
    float zv = 0.f, ho = 0.f;

    for (int t = 0; t < Sc; t++) {
        const unsigned par = (unsigned)(t & 1);

        // prefetch x-projection inputs (one per owning warp)
        float px = 0.f, pg = 0.f;
        if (warp < n1) {
            int cc = bid + warp * NB;
            bool isz = (warp < n2);
            int j = isz ? cc : cc - 1024;
            px = isz ? __ldcg(&g_xz[((size_t)t * Hc + j) * Bc + lane])
                     : __ldcg(&g_xr[((size_t)t * Hc + j) * Bc + lane]);
        }
        if (warp < n2) {
            int j = bid + warp * NB;
            pg = __ldcg(&g_xg[((size_t)t * Hc + j) * Bc + lane]);
        }

        // ---- phase 1 partials: 8 slots x 128 k per warp ----
        mb_wait(mb0 + (kq1 >> 1) * 8, par);
        float a[8];
#pragma unroll
        for (int c = 0; c < 8; c++) a[c] = 0.f;
        {
            const float* hp = buf + kq1 * 128 * Bc + lane;
#pragma unroll 2
            for (int k4 = 0; k4 < 32; k4++) {
                float v0 = hp[0], v1 = hp[Bc], v2 = hp[2 * Bc], v3 = hp[3 * Bc];
#pragma unroll
                for (int i = 0; i < 8; i++) {
                    float4 w = wb1[i * rowStep + k4];
                    a[i] += v0 * w.x; a[i] += v1 * w.y;
                    a[i] += v2 * w.z; a[i] += v3 * w.w;
                }
                hp += 4 * Bc;
            }
        }
        // store cross-kq partials (skip own diagonal c == kq1)
#pragma unroll
        for (int c = 0; c < 8; c++) {
            if (c != kq1)
                red_sm[(size_t)(warp * 7 + (c < kq1 ? c : c - 1)) * 32 + lane] = a[c];
        }
        __syncthreads();

        // finalize phase 1: warp w -> slot w (own partial in a[cw])
        if (warp < n1) {
            float acc = a[cw] + px;
            int gbase = g1 * 8;
#pragma unroll
            for (int q = 0; q < 8; q++) {
                int wp = gbase + q;
                if (q != cw)
                    acc += red_sm[(size_t)(wp * 7 + (cw < q ? cw : cw - 1)) * 32 + lane];
            }
            float val = sigm(acc);
            int cc = bid + warp * NB;
            bool isz = (warp < n2);
            int j = isz ? cc : cc - 1024;
            float hv = buf[j * Bc + lane];
            if (isz) { zv = val; ho = hv; }
            else     { __stcg(&g_rh[j * Bc + lane], val * hv); }
        }
        ep++; grid_bar(bid, NB, ep);

        // kick off stage of r*h (overwrites buf; all P1 reads done at grid_bar)
        if (tid == 0) {
#pragma unroll
            for (int q = 0; q < 4; q++) {
                mb_expect(mbr0 + q * 8, 32768u);
                g2s(bufa + q * 32768u, g_rh + q * 8192, 32768u, mbr0 + q * 8);
            }
        }

        // ---- phase 2 partials: all n2 slots x 64 k per warp ----
        mb_wait(mbr0 + (kq2 >> 2) * 8, par);
        float b[7];
#pragma unroll
        for (int c = 0; c < 7; c++) b[c] = 0.f;
        {
            const float* hp = buf + kq2 * 64 * Bc + lane;
#pragma unroll 2
            for (int k4 = 0; k4 < 16; k4++) {
                float v0 = hp[0], v1 = hp[Bc], v2 = hp[2 * Bc], v3 = hp[3 * Bc];
#pragma unroll
                for (int i = 0; i < 7; i++) {
                    float4 w = wb2[i * rowStep + k4];
                    b[i] += v0 * w.x; b[i] += v1 * w.y;
                    b[i] += v2 * w.z; b[i] += v3 * w.w;
                }
                hp += 4 * Bc;
            }
        }
#pragma unroll
        for (int c = 0; c < 7; c++)
            red_sm[(size_t)(warp * 7 + c) * 32 + lane] = b[c];
        __syncthreads();

        // finalize phase 2: warp w -> g-slot w (zv/ho carried from phase 1)
        if (warp < n2) {
            float acc = pg;
#pragma unroll
            for (int p = 0; p < 16; p++)
                acc += red_sm[(size_t)(p * 7 + warp) * 32 + lane];
            float gg = fast_tanh(acc);
            float hn = zv * ho + (1.0f - zv) * gg;
            int j = bid + warp * NB;
            __stcg(&g_h[j * Bc + lane], hn);
            g_y[((size_t)t * Hc + j) * Bc + lane] = hn;
        }
        ep++; grid_bar(bid, NB, ep);

        // kick off stage of h(t) for step t+1 (overwrites buf; P2 reads done)
        if (tid == 0 && t + 1 < Sc) {
#pragma unroll
            for (int q = 0; q < 4; q++) {
                mb_expect(mb0 + q * 8, 32768u);
                g2s(bufa + q * 32768u, g_h + q * 8192, 32768u, mb0 + q * 8);
            }
        }
    }

    // write final hidden state for this layer: d_out[HID_OFF + b*2H + layer*H + j]
    for (int s = warp; s < n2; s += 16) {
        int j = bid + s * NB;
        dout[HID_OFF + (size_t)lane * (2 * Hc) + (size_t)layer * Hc + j] =
            __ldcg(&g_h[j * Bc + lane]);
    }
}

// ---------------- host ----------------
extern "C" void kernel_launch(void* const* d_in, const int* in_sizes, int n_in,
                              void* d_out, int out_size) {
    const float* x    = (const float*)d_in[0];
    const float* Wxz0 = (const float*)d_in[1];
    const float* bxz0 = (const float*)d_in[2];
    const float* Whz0 = (const float*)d_in[3];
    const float* Wxr0 = (const float*)d_in[4];
    const float* bxr0 = (const float*)d_in[5];
    const float* Whr0 = (const float*)d_in[6];
    const float* Wxg0 = (const float*)d_in[7];
    const float* bxg0 = (const float*)d_in[8];
    const float* Whg0 = (const float*)d_in[9];
    const float* Wxz1 = (const float*)d_in[10];
    const float* bxz1 = (const float*)d_in[11];
    const float* Whz1 = (const float*)d_in[12];
    const float* Wxr1 = (const float*)d_in[13];
    const float* bxr1 = (const float*)d_in[14];
    const float* Whr1 = (const float*)d_in[15];
    const float* Wxg1 = (const float*)d_in[16];
    const float* bxg1 = (const float*)d_in[17];
    const float* Whg1 = (const float*)d_in[18];
    const float* Wout = (const float*)d_in[19];
    const float* bout = (const float*)d_in[20];
    float* out = (float*)d_out;

    int dev = 0;
    cudaGetDevice(&dev);
    int sm = 148;
    cudaDeviceGetAttribute(&sm, cudaDevAttrMultiProcessorCount, dev);
    int NB = (sm < 148) ? sm : 148;
    int slots = (2048 + NB - 1) / NB + (1024 + NB - 1) / NB;
    size_t smemB = ((size_t)Hc * Bc + (size_t)slots * Hc + (size_t)REDROWS * 32 + 16)
                   * sizeof(float);
    cudaFuncSetAttribute(recur_kernel, cudaFuncAttributeMaxDynamicSharedMemorySize, (int)smemB);

    dim3 pg(Sc, Hc / 128, 3);

    // Layer 0
    proj_kernel<<<pg, 256>>>(x, Wxz0, bxz0, Wxr0, bxr0, Wxg0, bxg0, Ic, 0);
    recur_kernel<<<NB, THREADS, smemB>>>(Whz0, Whr0, Whg0, 0, out);
    // Layer 1 (input projections read g_y written by layer-0 recurrence)
    proj_kernel<<<pg, 256>>>(x, Wxz1, bxz1, Wxr1, bxr1, Wxg1, bxg1, Hc, 1);
    recur_kernel<<<NB, THREADS, smemB>>>(Whz1, Whr1, Whg1, 1, out);
    // Output projection
    dim3 og(Sc, Oc / 128, 1);
    outproj_kernel<<<og, 256>>>(Wout, bout, out);
}